// round 16
// baseline (speedup 1.0000x reference)
#include <cuda_runtime.h>
#include <cuda_bf16.h>
#include <math.h>

#define NN 65536        // 256*256
#define NDIM 256
#define DEG_S 24        // Chebyshev degree for x^t / x^-t
#define NB 296          // 148 SMs x 2 blocks, co-resident by construction
#define NGRP 8
#define GRPSZ 37        // 296 = 8 * 37

// Buffer map (each 256x256 fp32):
//  0      : identity
//  1..24  : T_j (Chebyshev basis of Gtilde; T1 = Gtilde)
//  25     : X (Newton scratch)
//  26/27  : Minv ping-pong
//  28     : P     29 : Pinv
__device__ float g_buf[(size_t)30 * NN];
__device__ float g_params[8];     // [2]=aS+bS [3]=1/(bS-aS) [4]=aS [5]=bS
__device__ float g_ct[256 * 26];  // per-step x^t  coeffs (25 used)
__device__ float g_di[256 * 26];  // per-step x^-t coeffs (25 used)
__device__ float g_lam[256];      // per-batch lambda_max lower bounds

// two-level grid barrier state (self-resetting counters)
__device__ unsigned g_cnt[NGRP];
__device__ unsigned g_master;
__device__ volatile unsigned g_sense;

// Doubling-tree tasks {A,B,C,mode}: mode -2 => C=2AB-I, >=0 => C=2AB-buf[mode]
__constant__ int4 c_tasks[23] = {
    {1,1,2,-2},                                                 // L1
    {2,1,3,1},{2,2,4,-2},                                       // L2
    {3,2,5,1},{3,3,6,-2},{4,3,7,1},{4,4,8,-2},                  // L3
    {5,4,9,1},{5,5,10,-2},{6,5,11,1},{6,6,12,-2},               // L4
    {7,6,13,1},{7,7,14,-2},{8,7,15,1},{8,8,16,-2},
    {9,8,17,1},{9,9,18,-2},{10,9,19,1},{10,10,20,-2},           // L5
    {11,10,21,1},{11,11,22,-2},{12,11,23,1},{12,12,24,-2}
};

// ---------------------------------------------------------------------------
// Power iteration: lower bound on lambda_max(f_b). One block per batch.
// ---------------------------------------------------------------------------
__global__ void __launch_bounds__(256) pow_kernel(const float* __restrict__ f) {
    int b = blockIdx.x;
    const float* fb = f + (size_t)b * NN;
    __shared__ float v[256], w[256];
    __shared__ float redB[8], bc[2];
    int tid = threadIdx.x, lane = tid & 31, wp = tid >> 5;
    v[tid] = 1.0f;
    __syncthreads();
    for (int it = 0; it < 100; ++it) {
        for (int rr = wp * 32; rr < wp * 32 + 32; ++rr) {
            const float* row = fb + rr * NDIM;
            float s = 0.f;
            #pragma unroll
            for (int j = 0; j < 8; j++) s += row[lane + 32 * j] * v[lane + 32 * j];
            #pragma unroll
            for (int o = 16; o; o >>= 1) s += __shfl_down_sync(0xffffffffu, s, o);
            if (lane == 0) w[rr] = s;
        }
        __syncthreads();
        float wi = w[tid];
        float p2 = wi * wi;
        #pragma unroll
        for (int o = 16; o; o >>= 1) p2 += __shfl_down_sync(0xffffffffu, p2, o);
        if (lane == 0) redB[wp] = p2;
        __syncthreads();
        if (tid == 0) {
            float s2 = 0.f;
            for (int i = 0; i < 8; i++) s2 += redB[i];
            float nrm = sqrtf(fmaxf(s2, 1e-30f));
            bc[0] = nrm; bc[1] = 1.0f / nrm;
        }
        __syncthreads();
        v[tid] = w[tid] * bc[1];
        __syncthreads();
        if (it == 99 && tid == 0) g_lam[b] = bc[0];
        __syncthreads();
    }
}

// ---------------------------------------------------------------------------
// Interval parameters (1 thread, fp64)
// ---------------------------------------------------------------------------
__global__ void coefA_kernel() {
    double m = 1.0;
    for (int i = 0; i < 256; i++) { double x = (double)g_lam[i]; if (x > m) m = x; }
    double bM = 1.05 * m + 0.01; if (bM < 1.3) bM = 1.3;
    double bS = bM / 0.93, aS = 0.93 / bM;
    g_params[2] = (float)(aS + bS); g_params[3] = (float)(1.0 / (bS - aS));
    g_params[4] = (float)aS;        g_params[5] = (float)bS;
}

// ---------------------------------------------------------------------------
// Per-step Chebyshev coeffs of x^{t_k} AND x^{-t_k} on [aS,bS]; block k, fp64
// ---------------------------------------------------------------------------
__global__ void __launch_bounds__(64) coefT_kernel(const float* __restrict__ wts) {
    const double PI = 3.14159265358979323846;
    int k = blockIdx.x, i = threadIdx.x;
    __shared__ double fp[64], fm[64];
    double aS = (double)g_params[4], bS = (double)g_params[5];
    double w0 = (double)wts[2 * k], w1 = (double)wts[2 * k + 1];
    double t = 1.0 / (1.0 + exp(w0 - w1));   // softmax(weights)[:,1]
    double th = (i + 0.5) * PI / 64.0;
    double x = 0.5 * (aS + bS) + 0.5 * (bS - aS) * cos(th);
    double xp = pow(x, t);
    fp[i] = xp; fm[i] = 1.0 / xp;
    __syncthreads();
    if (i <= DEG_S) {
        double sp = 0.0, sm = 0.0;
        for (int n = 0; n < 64; n++) {
            double thn = (n + 0.5) * PI / 64.0;
            double c = cos((double)i * thn);
            sp += c * fp[n]; sm += c * fm[n];
        }
        double sc = ((i == 0) ? 1.0 : 2.0) / 64.0;
        g_ct[k * 26 + i] = (float)(sc * sp);
        g_di[k * 26 + i] = (float)(sc * sm);
    }
}

// ---------------------------------------------------------------------------
// Two-level grid barrier. Counters self-reset; sense seeded from g_sense.
// ---------------------------------------------------------------------------
__device__ __forceinline__ void gsync(unsigned& sense) {
    __syncthreads();
    if (threadIdx.x == 0) {
        sense ^= 1u;
        __threadfence();
        unsigned grp = blockIdx.x & (NGRP - 1);
        if (atomicAdd(&g_cnt[grp], 1u) == GRPSZ - 1u) {
            g_cnt[grp] = 0u;
            __threadfence();
            if (atomicAdd(&g_master, 1u) == NGRP - 1u) {
                g_master = 0u;
                __threadfence();
                g_sense = sense;
            }
        }
        while (g_sense != sense) { __nanosleep(64); }
        __threadfence();
    }
    __syncthreads();
}

// ---------------------------------------------------------------------------
// 64x32 tile mm machinery; block=256 threads, 4x2 outputs per thread.
// FFMA2 (fma.rn.f32x2) inner loop: accumulators pair over ROWS.
//  As[kk][row] transposed  -> ld.shared.v2.u64 gives (row2i,row2i+1) pairs.
//  Bs duplicated (b,b)     -> ld.shared.v2.u64 gives broadcast pairs.
// ---------------------------------------------------------------------------
__device__ __forceinline__ float4 ldA4(const float* __restrict__ A, int rowBase, int k0, int v) {
    int row = v >> 3, kq = v & 7;
    return *(const float4*)(A + (size_t)(rowBase + row) * NDIM + k0 + 4 * kq);
}
__device__ __forceinline__ float4 ldB4(const float* __restrict__ B, int colBase, int k0, int v) {
    int kr = v >> 3, cq = v & 7;
    return *(const float4*)(B + (size_t)(k0 + kr) * NDIM + colBase + 4 * cq);
}
__device__ __forceinline__ void stA(float (*As)[68], int v, float4 a) {
    int row = v >> 3, kq = v & 7;
    As[4 * kq + 0][row] = a.x; As[4 * kq + 1][row] = a.y;
    As[4 * kq + 2][row] = a.z; As[4 * kq + 3][row] = a.w;
}
// duplicate each B element: Bs2[kr][2c..2c+1] = (b_c, b_c)
__device__ __forceinline__ void stB(float (*Bs)[72], int v, float4 b) {
    int kr = v >> 3, cq = v & 7;
    float4 lo = make_float4(b.x, b.x, b.y, b.y);
    float4 hi = make_float4(b.z, b.z, b.w, b.w);
    *(float4*)&Bs[kr][8 * cq]     = lo;
    *(float4*)&Bs[kr][8 * cq + 4] = hi;
}
__device__ __forceinline__ void inner32(const float (*As)[68], const float (*Bs)[72],
                                        int tx, int ty, unsigned long long* acc) {
    #pragma unroll
    for (int kk = 0; kk < 32; kk++) {
        ulonglong2 a = *(const ulonglong2*)&As[kk][4 * ty];   // (r0,r1),(r2,r3)
        ulonglong2 b = *(const ulonglong2*)&Bs[kk][4 * tx];   // (c0,c0),(c1,c1)
        asm("fma.rn.f32x2 %0, %1, %2, %0;" : "+l"(acc[0]) : "l"(a.x), "l"(b.x));
        asm("fma.rn.f32x2 %0, %1, %2, %0;" : "+l"(acc[1]) : "l"(a.x), "l"(b.y));
        asm("fma.rn.f32x2 %0, %1, %2, %0;" : "+l"(acc[2]) : "l"(a.y), "l"(b.x));
        asm("fma.rn.f32x2 %0, %1, %2, %0;" : "+l"(acc[3]) : "l"(a.y), "l"(b.y));
    }
}
__device__ __forceinline__ void unpack2(unsigned long long p, float& lo, float& hi) {
    asm("mov.b64 {%0,%1}, %2;" : "=f"(lo), "=f"(hi) : "l"(p));
}

// Epilogue modes
#define EP_TREE_I  0   // C = 2AB - I
#define EP_TREE_D  1   // C = 2AB - D
#define EP_PLAIN   2   // C = AB
#define EP_SCALE   3   // C = (2AB - c2*I)*c3
#define EP_NEWTON  4   // C = 2D - AB

__device__ __forceinline__ void mm_tile(const float* __restrict__ A, const float* __restrict__ B,
                                        const float* __restrict__ D, float* __restrict__ C,
                                        int mode, float c2, float c3,
                                        int rowBase, int colBase,
                                        float (*As)[68], float (*Bs)[72]) {
    int t = threadIdx.x, tx = t & 15, ty = t >> 4;
    unsigned long long acc[4] = {0ull, 0ull, 0ull, 0ull};
    float4 a0 = ldA4(A, rowBase, 0, t), a1 = ldA4(A, rowBase, 0, t + 256);
    float4 b0 = ldB4(B, colBase, 0, t);
    #pragma unroll
    for (int c8 = 0; c8 < 8; c8++) {
        __syncthreads();
        stA(As, t, a0); stA(As, t + 256, a1); stB(Bs, t, b0);
        __syncthreads();
        if (c8 < 7) {
            int k0 = (c8 + 1) * 32;
            a0 = ldA4(A, rowBase, k0, t); a1 = ldA4(A, rowBase, k0, t + 256);
            b0 = ldB4(B, colBase, k0, t);
        }
        inner32(As, Bs, tx, ty, acc);
    }
    // unpack: acc[0]=(r0,r1)c0 acc[1]=(r0,r1)c1 acc[2]=(r2,r3)c0 acc[3]=(r2,r3)c1
    float v[4][2];   // v[i] = (c0, c1) for row i
    unpack2(acc[0], v[0][0], v[1][0]);
    unpack2(acc[1], v[0][1], v[1][1]);
    unpack2(acc[2], v[2][0], v[3][0]);
    unpack2(acc[3], v[2][1], v[3][1]);
    int r0 = rowBase + 4 * ty, c0 = colBase + 2 * tx;
    #pragma unroll
    for (int i = 0; i < 4; i++) {
        int r = r0 + i;
        size_t idx = (size_t)r * NDIM + c0;
        float2 o;
        if (mode == EP_PLAIN) {
            o.x = v[i][0]; o.y = v[i][1];
        } else if (mode == EP_TREE_I) {
            o.x = 2.f * v[i][0] - ((r == c0    ) ? 1.f : 0.f);
            o.y = 2.f * v[i][1] - ((r == c0 + 1) ? 1.f : 0.f);
        } else if (mode == EP_TREE_D) {
            o.x = 2.f * v[i][0] - D[idx];
            o.y = 2.f * v[i][1] - D[idx + 1];
        } else if (mode == EP_SCALE) {
            o.x = (2.f * v[i][0] - ((r == c0    ) ? c2 : 0.f)) * c3;
            o.y = (2.f * v[i][1] - ((r == c0 + 1) ? c2 : 0.f)) * c3;
        } else { // EP_NEWTON
            o.x = 2.f * D[idx]     - v[i][0];
            o.y = 2.f * D[idx + 1] - v[i][1];
        }
        *(float2*)(C + idx) = o;
    }
}

__device__ __forceinline__ void tree_level(int base, int ntasks,
                                           float (*As)[68], float (*Bs)[72]) {
    for (int g = blockIdx.x; g < ntasks * 32; g += NB) {
        int4 T = c_tasks[base + (g >> 5)];
        int tile = g & 31;
        int rowBase = (tile >> 3) << 6, colBase = (tile & 7) << 5;
        mm_tile(g_buf + (size_t)T.x * NN, g_buf + (size_t)T.y * NN,
                (T.w >= 0) ? g_buf + (size_t)T.w * NN : (const float*)0,
                g_buf + (size_t)T.z * NN,
                (T.w == -2) ? EP_TREE_I : EP_TREE_D, 0.f, 0.f,
                rowBase, colBase, As, Bs);
    }
}

// ---------------------------------------------------------------------------
// Persistent fused scan kernel
// ---------------------------------------------------------------------------
__global__ void __launch_bounds__(256, 2) fused_kernel(const float* __restrict__ f,
                                                       float* __restrict__ out) {
    __shared__ __align__(16) float As[32][68];
    __shared__ __align__(16) float Bs[32][72];
    __shared__ float ctS[32];
    __shared__ float diS[32];
    int t = threadIdx.x;
    unsigned sense = g_sense;          // robust across graph replays, any parity
    const float c2 = g_params[2], c3 = g_params[3];

    // init: buf0 = I; Minv(26) = I
    for (int e = blockIdx.x * 256 + t; e < NN; e += NB * 256) {
        int r = e >> 8, c = e & 255;
        float d = (r == c) ? 1.f : 0.f;
        g_buf[e] = d;
        g_buf[(size_t)26 * NN + e] = d;
    }
    gsync(sense);

    int curI = 26;
    for (int k = 0; k < 256; ++k) {
        const float* fk = f + (size_t)k * NN;
        float* outk = out + (size_t)k * NN;
        const float* Minv = g_buf + (size_t)curI * NN;
        int nxtI = 53 - curI;
        float* MinvN = g_buf + (size_t)nxtI * NN;

        // stage per-step coefficients into smem (used by combine phase)
        if (t < 32) {
            ctS[t] = (t <= DEG_S) ? g_ct[k * 26 + t] : 0.f;
            diS[t] = (t <= DEG_S) ? g_di[k * 26 + t] : 0.f;
        }

        // Phase G: T1 = (2*(Minv*fk) - c2*I)*c3
        for (int g = blockIdx.x; g < 32; g += NB) {
            int rowBase = (g >> 3) << 6, colBase = (g & 7) << 5;
            mm_tile(Minv, fk, 0, g_buf + (size_t)NN, EP_SCALE, c2, c3,
                    rowBase, colBase, As, Bs);
        }
        gsync(sense);

        // TS Chebyshev tree (deg 24, 5 levels)
        tree_level(0, 1, As, Bs);  gsync(sense);
        tree_level(1, 2, As, Bs);  gsync(sense);
        tree_level(3, 4, As, Bs);  gsync(sense);
        tree_level(7, 8, As, Bs);  gsync(sense);
        tree_level(15, 8, As, Bs); gsync(sense);

        // Phase C: materialize P(28) and Pinv(29) elementwise (each T_j read once)
        {
            float* P  = g_buf + (size_t)28 * NN;
            float* Pi = g_buf + (size_t)29 * NN;
            for (int e = blockIdx.x * 256 + t; e < NN; e += NB * 256) {
                int r = e >> 8, c = e & 255;
                float sp = (r == c) ? ctS[0] : 0.f;
                float si = (r == c) ? diS[0] : 0.f;
                #pragma unroll
                for (int j = 1; j <= DEG_S; j++) {
                    float tv = g_buf[(size_t)j * NN + e];
                    sp += ctS[j] * tv;
                    si += diS[j] * tv;
                }
                P[e] = sp; Pi[e] = si;
            }
        }
        gsync(sense);

        // Phase D+E (one barrier): out[k] = Mprev*P ; MinvN = Pinv*Minv
        {
            const float* Mprev = (k == 0) ? g_buf : (out + (size_t)(k - 1) * NN);
            const float* P  = g_buf + (size_t)28 * NN;
            const float* Pi = g_buf + (size_t)29 * NN;
            for (int g = blockIdx.x; g < 64; g += NB) {
                int tile = g & 31;
                int rowBase = (tile >> 3) << 6, colBase = (tile & 7) << 5;
                if (g < 32)
                    mm_tile(Mprev, P, 0, outk, EP_PLAIN, 0.f, 0.f,
                            rowBase, colBase, As, Bs);
                else
                    mm_tile(Pi, Minv, 0, MinvN, EP_PLAIN, 0.f, 0.f,
                            rowBase, colBase, As, Bs);
            }
        }
        gsync(sense);
        curI = nxtI;

        // Newton refresh of Minv every 8 steps: Minv <- Minv*(2I - M*Minv)
        if ((k & 7) == 7) {
            const float* Mc = g_buf + (size_t)curI * NN;
            for (int g = blockIdx.x; g < 32; g += NB) {
                int rowBase = (g >> 3) << 6, colBase = (g & 7) << 5;
                mm_tile(outk, Mc, 0, g_buf + (size_t)25 * NN, EP_PLAIN, 0.f, 0.f,
                        rowBase, colBase, As, Bs);
            }
            gsync(sense);
            int nx2 = 53 - curI;
            for (int g = blockIdx.x; g < 32; g += NB) {
                int rowBase = (g >> 3) << 6, colBase = (g & 7) << 5;
                mm_tile(Mc, g_buf + (size_t)25 * NN, Mc,
                        g_buf + (size_t)nx2 * NN, EP_NEWTON, 0.f, 0.f,
                        rowBase, colBase, As, Bs);
            }
            gsync(sense);
            curI = nx2;
        }
    }
}

// ---------------------------------------------------------------------------
extern "C" void kernel_launch(void* const* d_in, const int* in_sizes, int n_in,
                              void* d_out, int out_size) {
    const float* f = (const float*)d_in[0];        // (256,1,256,256)
    const float* w = (const float*)d_in[1];        // (256,2)
    float* out = (float*)d_out;                    // (256,1,256,256)

    pow_kernel<<<256, 256>>>(f);
    coefA_kernel<<<1, 1>>>();
    coefT_kernel<<<256, 64>>>(w);
    fused_kernel<<<NB, 256>>>(f, out);
}